// round 10
// baseline (speedup 1.0000x reference)
#include <cuda_runtime.h>

#define N_AGENT 32
#define BATCH   8192
#define S_DIM   48
#define A_DIM   10
#define G_DIM   128
#define HID     36
#define TBF     256       // rows per feat block
#define TBC     256       // rows per comm block
#define NTHREADS 128

typedef unsigned long long ull;

// scratch (allocation-free rule: static __device__ arrays)
__device__ float d_sf[N_AGENT * BATCH * HID];      // 37.7 MB
__device__ float d_gf[BATCH * HID];                // 1.2 MB
// A packed per (i, slice): [kp(18)][ch(2)][12]: within 12: a_local(0..5)x(k even, k odd)
//   action a = ch*5 + a_local (a_local==5 is pad), k = 2*kp + parity
__device__ float d_A[N_AGENT * 4 * 432];
__device__ float d_beff[N_AGENT * A_DIM];

__device__ __forceinline__ ull fma2(ull a, ull b, ull c) {
    ull d;
    asm("fma.rn.f32x2 %0, %1, %2, %3;" : "=l"(d) : "l"(a), "l"(b), "l"(c));
    return d;
}
__device__ __forceinline__ ull splat2(float x) {
    ull r; asm("mov.b64 %0, {%1, %1};" : "=l"(r) : "f"(x)); return r;
}
__device__ __forceinline__ ull pack2(float x, float y) {
    ull r; asm("mov.b64 %0, {%1, %2};" : "=l"(r) : "f"(x), "f"(y)); return r;
}
__device__ __forceinline__ float2 unpack2(ull v) {
    float2 r; asm("mov.b64 {%0, %1}, %2;" : "=f"(r.x), "=f"(r.y) : "l"(v)); return r;
}
__device__ __forceinline__ float fast_tanh(float x) {
    float e, r;
    asm("ex2.approx.f32 %0, %1;" : "=f"(e) : "f"(x * 2.88539008177793f)); // 2*log2(e)
    asm("rcp.approx.f32 %0, %1;" : "=f"(r) : "f"(e + 1.0f));
    return 1.0f - 2.0f * r;
}

// ---------------------------------------------------------------------------
// feat: y==0 -> precompute packed A + beff; y in [1,32] -> agent MLP
// (split-output, 4 rows/thread); y==33 -> global feature.
// ---------------------------------------------------------------------------
#define FEAT_SMEM_FLOATS (3440 + TBF * 52)
#define FEAT_SMEM_BYTES  (FEAT_SMEM_FLOATS * 4)

__global__ void feat_kernel(const float* __restrict__ states,
                            const float* __restrict__ gs,
                            const float* __restrict__ W1, const float* __restrict__ b1,
                            const float* __restrict__ W2, const float* __restrict__ b2,
                            const float* __restrict__ Wg, const float* __restrict__ bg,
                            const float* __restrict__ Wv, const float* __restrict__ bv,
                            const float* __restrict__ Wact, const float* __restrict__ bact,
                            const float* __restrict__ topo)
{
    extern __shared__ __align__(16) float sm[];
    const int tid = threadIdx.x;
    const int yb  = blockIdx.y;

    if (yb == 0) {
        // ------- pre slice: packed A + beff for agent i = blockIdx.x -------
        const int i = blockIdx.x;
        float* sWa = sm;          // Wact_i [10][36]
        float* sWv = sm + 384;    // Wv     [36][36]
        for (int idx = tid; idx < A_DIM * HID; idx += NTHREADS)
            sWa[idx] = Wact[i * A_DIM * HID + idx];
        __syncthreads();
        for (int jj = 0; jj < 3; jj++) {
            const int j = (i + N_AGENT - 1 + jj) % N_AGENT;
            const float c = topo[i * N_AGENT + j];
            const float* gWv = Wv + (size_t)(i * N_AGENT + j) * HID * HID;
            for (int idx = tid; idx < HID * HID; idx += NTHREADS)
                sWv[idx] = c * gWv[idx];
            __syncthreads();
            for (int idx = tid; idx < 432; idx += NTHREADS) {
                const int kp = idx / 24, q = idx - kp * 24;
                const int ch = q / 12, w = q - ch * 12;
                const int al = w >> 1, par = w & 1;
                const int a = ch * 5 + al;
                const int k = 2 * kp + par;
                float acc = 0.f;
                if (al < 5) {
                    #pragma unroll
                    for (int g = 0; g < HID; g++)
                        acc += sWa[a * HID + g] * sWv[g * HID + k];
                }
                d_A[(i * 4 + jj) * 432 + idx] = acc;
            }
            __syncthreads();
        }
        // slot 3 = plain Wact in packed layout (global-feature term)
        for (int idx = tid; idx < 432; idx += NTHREADS) {
            const int kp = idx / 24, q = idx - kp * 24;
            const int ch = q / 12, w = q - ch * 12;
            const int al = w >> 1, par = w & 1;
            const int a = ch * 5 + al;
            const int k = 2 * kp + par;
            d_A[(i * 4 + 3) * 432 + idx] = (al < 5) ? sWa[a * HID + k] : 0.f;
        }
        if (tid < A_DIM) {
            float acc = bact[i * A_DIM + tid];
            for (int q = 0; q < 3; q++) {
                const int jq = (i + N_AGENT - 1 + q) % N_AGENT;
                const float cq = topo[i * N_AGENT + jq];
                const float* gbv = bv + (size_t)(i * N_AGENT + jq) * HID;
                #pragma unroll
                for (int g = 0; g < HID; g++)
                    acc += sWa[tid * HID + g] * (cq * gbv[g]);
            }
            d_beff[i * A_DIM + tid] = acc;
        }
        return;
    }

    const int r0 = blockIdx.x * TBF;

    if (yb <= N_AGENT) {
        // ------- agent MLP: 64 row-threads x 2 output-halves, 4 rows each -------
        const int ag = yb - 1;
        const int rt = tid & 63, ch = tid >> 6;
        float* W1T  = sm;           // [48][40] (outputs padded to 40)
        float* W2T  = sm + 1920;    // [36][40]
        float* b1p  = sm + 3360;    // [40]
        float* b2p  = sm + 3400;    // [40]
        float* tile = sm + 3440;    // states: [256][52]; h: [256][44]
        float4* tile4 = (float4*)tile;

        const float* gW1 = W1 + ag * HID * S_DIM;
        for (int idx = tid; idx < S_DIM * 40; idx += NTHREADS) {
            const int k = idx / 40, f = idx - k * 40;
            W1T[idx] = (f < HID) ? gW1[f * S_DIM + k] : 0.f;
        }
        const float* gW2 = W2 + ag * HID * HID;
        for (int idx = tid; idx < HID * 40; idx += NTHREADS) {
            const int k = idx / 40, f = idx - k * 40;
            W2T[idx] = (f < HID) ? gW2[f * HID + k] : 0.f;
        }
        if (tid < 40) {
            b1p[tid] = (tid < HID) ? b1[ag * HID + tid] : 0.f;
            b2p[tid] = (tid < HID) ? b2[ag * HID + tid] : 0.f;
        }
        const float4* gS4 = (const float4*)(states + (size_t)(ag * BATCH + r0) * S_DIM);
        for (int idx = tid; idx < TBF * (S_DIM / 4); idx += NTHREADS) {
            const int row = idx / 12, c4 = idx - row * 12;
            tile4[row * 13 + c4] = gS4[idx];
        }
        __syncthreads();

        // layer 1: acc[r][p] = outputs [ch*20, ch*20+20) for row rt+64r
        ull acc[4][10];
        {
            const ull* bb = (const ull*)(b1p + ch * 20);
            #pragma unroll
            for (int r = 0; r < 4; r++)
                #pragma unroll
                for (int p = 0; p < 10; p++) acc[r][p] = bb[p];
        }
        #pragma unroll
        for (int k4 = 0; k4 < S_DIM / 4; k4++) {
            float4 sv[4];
            #pragma unroll
            for (int r = 0; r < 4; r++) sv[r] = tile4[(rt + 64 * r) * 13 + k4];
            #pragma unroll
            for (int kk = 0; kk < 4; kk++) {
                const int k = k4 * 4 + kk;
                ull sk[4];
                #pragma unroll
                for (int r = 0; r < 4; r++) sk[r] = splat2(((const float*)&sv[r])[kk]);
                const ulonglong2* w = (const ulonglong2*)(W1T + k * 40 + ch * 20);
                #pragma unroll
                for (int p2 = 0; p2 < 5; p2++) {
                    ulonglong2 wv = w[p2];
                    #pragma unroll
                    for (int r = 0; r < 4; r++) {
                        acc[r][2*p2]   = fma2(wv.x, sk[r], acc[r][2*p2]);
                        acc[r][2*p2+1] = fma2(wv.y, sk[r], acc[r][2*p2+1]);
                    }
                }
            }
        }
        __syncthreads();   // states tile reads done
        // tanh -> h tile [256][44]
        #pragma unroll
        for (int r = 0; r < 4; r++) {
            float* hb = &tile[(rt + 64 * r) * 44 + ch * 20];
            #pragma unroll
            for (int p2 = 0; p2 < 5; p2++) {
                float2 x = unpack2(acc[r][2*p2]), y = unpack2(acc[r][2*p2+1]);
                ulonglong2 st;
                st.x = pack2(fast_tanh(x.x), fast_tanh(x.y));
                st.y = pack2(fast_tanh(y.x), fast_tanh(y.y));
                *(ulonglong2*)&hb[4 * p2] = st;
            }
        }
        __syncthreads();

        // layer 2
        {
            const ull* bb = (const ull*)(b2p + ch * 20);
            #pragma unroll
            for (int r = 0; r < 4; r++)
                #pragma unroll
                for (int p = 0; p < 10; p++) acc[r][p] = bb[p];
        }
        #pragma unroll
        for (int k4 = 0; k4 < HID / 4; k4++) {
            float4 sv[4];
            #pragma unroll
            for (int r = 0; r < 4; r++) sv[r] = tile4[(rt + 64 * r) * 11 + k4];
            #pragma unroll
            for (int kk = 0; kk < 4; kk++) {
                const int k = k4 * 4 + kk;
                ull sk[4];
                #pragma unroll
                for (int r = 0; r < 4; r++) sk[r] = splat2(((const float*)&sv[r])[kk]);
                const ulonglong2* w = (const ulonglong2*)(W2T + k * 40 + ch * 20);
                #pragma unroll
                for (int p2 = 0; p2 < 5; p2++) {
                    ulonglong2 wv = w[p2];
                    #pragma unroll
                    for (int r = 0; r < 4; r++) {
                        acc[r][2*p2]   = fma2(wv.x, sk[r], acc[r][2*p2]);
                        acc[r][2*p2+1] = fma2(wv.y, sk[r], acc[r][2*p2+1]);
                    }
                }
            }
        }
        // tanh + direct store (ch0: f0..19 = 5x16B; ch1: f20..35 = 4x16B)
        const int nst = ch ? 4 : 5;
        #pragma unroll
        for (int r = 0; r < 4; r++) {
            const int row = r0 + rt + 64 * r;
            float* o = d_sf + (size_t)(ag * BATCH + row) * HID + ch * 20;
            for (int p2 = 0; p2 < nst; p2++) {
                float2 x = unpack2(acc[r][2*p2]), y = unpack2(acc[r][2*p2+1]);
                ulonglong2 st;
                st.x = pack2(fast_tanh(x.x), fast_tanh(x.y));
                st.y = pack2(fast_tanh(y.x), fast_tanh(y.y));
                *(ulonglong2*)&o[4 * p2] = st;
            }
        }
    } else {
        // ------- global feature, 2 rows per thread -------
        float* WgT = sm;           // [128][36]
        float* bgs = sm + 4608;
        for (int idx = tid; idx < HID * G_DIM; idx += NTHREADS) {
            const int f = idx / G_DIM, k = idx - f * G_DIM;
            WgT[k * HID + f] = Wg[idx];
        }
        if (tid < HID) bgs[tid] = bg[tid];
        __syncthreads();
        ull acc0[18], acc1[18];
        {
            const ull* bu = (const ull*)bgs;
            #pragma unroll
            for (int p = 0; p < 18; p++) { acc0[p] = bu[p]; acc1[p] = bu[p]; }
        }
        const float4* g0 = (const float4*)(gs + (size_t)(r0 + tid) * G_DIM);
        const float4* g1 = (const float4*)(gs + (size_t)(r0 + tid + NTHREADS) * G_DIM);
        for (int k4 = 0; k4 < G_DIM / 4; k4++) {
            float4 vA = g0[k4];
            float4 vB = g1[k4];
            #pragma unroll
            for (int kk = 0; kk < 4; kk++) {
                const ull a_s = splat2(((const float*)&vA)[kk]);
                const ull b_s = splat2(((const float*)&vB)[kk]);
                const ulonglong2* w = (const ulonglong2*)&WgT[(k4 * 4 + kk) * HID];
                #pragma unroll
                for (int p2 = 0; p2 < 9; p2++) {
                    ulonglong2 wv = w[p2];
                    acc0[2*p2]   = fma2(wv.x, a_s, acc0[2*p2]);
                    acc0[2*p2+1] = fma2(wv.y, a_s, acc0[2*p2+1]);
                    acc1[2*p2]   = fma2(wv.x, b_s, acc1[2*p2]);
                    acc1[2*p2+1] = fma2(wv.y, b_s, acc1[2*p2+1]);
                }
            }
        }
        float* o0 = d_gf + (size_t)(r0 + tid) * HID;
        float* o1 = d_gf + (size_t)(r0 + tid + NTHREADS) * HID;
        #pragma unroll
        for (int p2 = 0; p2 < 9; p2++) {
            ulonglong2 s0, s1;
            s0.x = acc0[2*p2]; s0.y = acc0[2*p2+1];
            s1.x = acc1[2*p2]; s1.y = acc1[2*p2+1];
            *(ulonglong2*)&o0[p2 * 4] = s0;
            *(ulonglong2*)&o1[p2 * 4] = s1;
        }
    }
}

// ---------------------------------------------------------------------------
// comm: k-paired f32x2, 64 row-threads x 2 action-halves, 4 rows/thread.
// ---------------------------------------------------------------------------
struct SmemComm {
    float A[4 * 432];           // 6912 B, packed [jj][kp][ch][12]
    float be[16];
    float tile[TBC * HID];      // 36864 B, stride 36 (9 x 16B units, odd)
};

__global__ __launch_bounds__(NTHREADS)
void comm_kernel(float* __restrict__ out)
{
    __shared__ __align__(16) SmemComm sm;
    const int tid = threadIdx.x;
    const int rt  = tid & 63, ch = tid >> 6;
    const int r0  = blockIdx.x * TBC;
    const int i   = blockIdx.y;
    float4* tile4 = (float4*)sm.tile;

    const float4* gA = (const float4*)(d_A + (size_t)i * 4 * 432);
    float4* sA4 = (float4*)sm.A;
    for (int idx = tid; idx < 432; idx += NTHREADS) sA4[idx] = gA[idx];
    if (tid < A_DIM) sm.be[tid] = d_beff[i * A_DIM + tid];
    __syncthreads();

    ull acc[4][5];
    #pragma unroll
    for (int r = 0; r < 4; r++)
        #pragma unroll
        for (int a = 0; a < 5; a++) acc[r][a] = 0ull;

    #pragma unroll
    for (int jj = 0; jj < 4; jj++) {
        const float* src;
        if (jj < 3) {
            const int j = (i + N_AGENT - 1 + jj) % N_AGENT;
            src = d_sf + (size_t)(j * BATCH + r0) * HID;
        } else {
            src = d_gf + (size_t)r0 * HID;
        }
        const float4* src4 = (const float4*)src;
        for (int idx = tid; idx < TBC * HID / 4; idx += NTHREADS) tile4[idx] = src4[idx];
        __syncthreads();

        const float* Ab = &sm.A[jj * 432];
        #pragma unroll
        for (int i4 = 0; i4 < 9; i4++) {
            ulonglong2 su[4];
            #pragma unroll
            for (int r = 0; r < 4; r++) {
                float4 sv = tile4[(rt + 64 * r) * 9 + i4];
                su[r] = *(ulonglong2*)&sv;
            }
            #pragma unroll
            for (int h = 0; h < 2; h++) {
                const int kp = 2 * i4 + h;
                const float* wp = Ab + kp * 24 + ch * 12;
                ulonglong2 w01 = *(const ulonglong2*)wp;
                ulonglong2 w23 = *(const ulonglong2*)(wp + 4);
                ull w4 = *(const ull*)(wp + 8);
                #pragma unroll
                for (int r = 0; r < 4; r++) {
                    const ull s = h ? su[r].y : su[r].x;
                    acc[r][0] = fma2(w01.x, s, acc[r][0]);
                    acc[r][1] = fma2(w01.y, s, acc[r][1]);
                    acc[r][2] = fma2(w23.x, s, acc[r][2]);
                    acc[r][3] = fma2(w23.y, s, acc[r][3]);
                    acc[r][4] = fma2(w4,    s, acc[r][4]);
                }
            }
        }
        __syncthreads();   // tile reads done before next overwrite
    }

    #pragma unroll
    for (int r = 0; r < 4; r++) {
        const int row = r0 + rt + 64 * r;
        float acts[5];
        #pragma unroll
        for (int al = 0; al < 5; al++) {
            float2 p = unpack2(acc[r][al]);
            acts[al] = fast_tanh(p.x + p.y + sm.be[ch * 5 + al]);
        }
        // alignment-aware epilogue: base offset i*10 is even; ch1 adds +5 (odd),
        // so ch1 writes {scalar, f2@+6, f2@+8} to keep all float2 stores 8B-aligned.
        float* o = out + (size_t)row * (N_AGENT * A_DIM) + i * A_DIM + ch * 5;
        if (ch == 0) {
            *(float2*)o       = make_float2(acts[0], acts[1]);
            *(float2*)(o + 2) = make_float2(acts[2], acts[3]);
            o[4] = acts[4];
        } else {
            o[0] = acts[0];
            *(float2*)(o + 1) = make_float2(acts[1], acts[2]);
            *(float2*)(o + 3) = make_float2(acts[3], acts[4]);
        }
    }
}

extern "C" void kernel_launch(void* const* d_in, const int* in_sizes, int n_in,
                              void* d_out, int out_size)
{
    const float* states = (const float*)d_in[0];
    const float* gs     = (const float*)d_in[1];
    const float* W1     = (const float*)d_in[2];
    const float* b1     = (const float*)d_in[3];
    const float* W2     = (const float*)d_in[4];
    const float* b2     = (const float*)d_in[5];
    const float* Wv     = (const float*)d_in[6];
    const float* bv     = (const float*)d_in[7];
    const float* Wg     = (const float*)d_in[8];
    const float* bg     = (const float*)d_in[9];
    const float* Wact   = (const float*)d_in[10];
    const float* bact   = (const float*)d_in[11];
    const float* topo   = (const float*)d_in[12];

    cudaFuncSetAttribute(feat_kernel, cudaFuncAttributeMaxDynamicSharedMemorySize,
                         FEAT_SMEM_BYTES);
    feat_kernel<<<dim3(BATCH / TBF, N_AGENT + 2), NTHREADS, FEAT_SMEM_BYTES>>>(
        states, gs, W1, b1, W2, b2, Wg, bg, Wv, bv, Wact, bact, topo);
    comm_kernel<<<dim3(BATCH / TBC, N_AGENT), NTHREADS>>>((float*)d_out);
}

// round 11
// speedup vs baseline: 1.1201x; 1.1201x over previous
#include <cuda_runtime.h>

#define N_AGENT 32
#define BATCH   8192
#define S_DIM   48
#define A_DIM   10
#define G_DIM   128
#define HID     36
#define TBF     128       // rows per feat block
#define TBC     256       // rows per comm block
#define NTHREADS 128

typedef unsigned long long ull;

// Transposed pair-interleaved activations:
//   d_sfT: [agent][kp(18)][row(8192)] of 8B pairs (f=2kp, f=2kp+1)
//   d_gfT: [kp(18)][row(8192)] of 8B pairs
__device__ float d_sfT[N_AGENT * 18 * BATCH * 2];   // 37.7 MB
__device__ float d_gfT[18 * BATCH * 2];             // 1.2 MB
// A packed per (i, slice): [kp(18)][ch(2)][12]: within 12: a_local(0..5)x(k even, k odd)
__device__ float d_A[N_AGENT * 4 * 432];
__device__ float d_beff[N_AGENT * A_DIM];

__device__ __forceinline__ ull fma2(ull a, ull b, ull c) {
    ull d;
    asm("fma.rn.f32x2 %0, %1, %2, %3;" : "=l"(d) : "l"(a), "l"(b), "l"(c));
    return d;
}
__device__ __forceinline__ ull splat2(float x) {
    ull r; asm("mov.b64 %0, {%1, %1};" : "=l"(r) : "f"(x)); return r;
}
__device__ __forceinline__ ull pack2(float x, float y) {
    ull r; asm("mov.b64 %0, {%1, %2};" : "=l"(r) : "f"(x), "f"(y)); return r;
}
__device__ __forceinline__ float2 unpack2(ull v) {
    float2 r; asm("mov.b64 {%0, %1}, %2;" : "=f"(r.x), "=f"(r.y) : "l"(v)); return r;
}
__device__ __forceinline__ float fast_tanh(float x) {
    float e, r;
    asm("ex2.approx.f32 %0, %1;" : "=f"(e) : "f"(x * 2.88539008177793f)); // 2*log2(e)
    asm("rcp.approx.f32 %0, %1;" : "=f"(r) : "f"(e + 1.0f));
    return 1.0f - 2.0f * r;
}
__device__ __forceinline__ ull tanh2(ull v) {
    float2 p = unpack2(v);
    return pack2(fast_tanh(p.x), fast_tanh(p.y));
}

// ---------------------------------------------------------------------------
// feat: y==0 -> precompute packed A + beff; y in [1,32] -> agent MLP
// (split-output, 2 rows/thread, TBF=128); y==33 -> global feature.
// ---------------------------------------------------------------------------
#define FEAT_SMEM_FLOATS (3440 + TBF * 52)
#define FEAT_SMEM_BYTES  (FEAT_SMEM_FLOATS * 4)

__global__ void feat_kernel(const float* __restrict__ states,
                            const float* __restrict__ gs,
                            const float* __restrict__ W1, const float* __restrict__ b1,
                            const float* __restrict__ W2, const float* __restrict__ b2,
                            const float* __restrict__ Wg, const float* __restrict__ bg,
                            const float* __restrict__ Wv, const float* __restrict__ bv,
                            const float* __restrict__ Wact, const float* __restrict__ bact,
                            const float* __restrict__ topo)
{
    extern __shared__ __align__(16) float sm[];
    const int tid = threadIdx.x;
    const int yb  = blockIdx.y;

    if (yb == 0) {
        // ------- pre slice: packed A + beff for agent i = blockIdx.x -------
        const int i = blockIdx.x;
        if (i >= N_AGENT) return;
        float* sWa = sm;          // Wact_i [10][36]
        float* sWv = sm + 384;    // Wv     [36][36]
        for (int idx = tid; idx < A_DIM * HID; idx += NTHREADS)
            sWa[idx] = Wact[i * A_DIM * HID + idx];
        __syncthreads();
        for (int jj = 0; jj < 3; jj++) {
            const int j = (i + N_AGENT - 1 + jj) % N_AGENT;
            const float c = topo[i * N_AGENT + j];
            const float* gWv = Wv + (size_t)(i * N_AGENT + j) * HID * HID;
            for (int idx = tid; idx < HID * HID; idx += NTHREADS)
                sWv[idx] = c * gWv[idx];
            __syncthreads();
            for (int idx = tid; idx < 432; idx += NTHREADS) {
                const int kp = idx / 24, q = idx - kp * 24;
                const int ch = q / 12, w = q - ch * 12;
                const int al = w >> 1, par = w & 1;
                const int a = ch * 5 + al;
                const int k = 2 * kp + par;
                float acc = 0.f;
                if (al < 5) {
                    #pragma unroll
                    for (int g = 0; g < HID; g++)
                        acc += sWa[a * HID + g] * sWv[g * HID + k];
                }
                d_A[(i * 4 + jj) * 432 + idx] = acc;
            }
            __syncthreads();
        }
        // slot 3 = plain Wact in packed layout (global-feature term)
        for (int idx = tid; idx < 432; idx += NTHREADS) {
            const int kp = idx / 24, q = idx - kp * 24;
            const int ch = q / 12, w = q - ch * 12;
            const int al = w >> 1, par = w & 1;
            const int a = ch * 5 + al;
            const int k = 2 * kp + par;
            d_A[(i * 4 + 3) * 432 + idx] = (al < 5) ? sWa[a * HID + k] : 0.f;
        }
        if (tid < A_DIM) {
            float acc = bact[i * A_DIM + tid];
            for (int q = 0; q < 3; q++) {
                const int jq = (i + N_AGENT - 1 + q) % N_AGENT;
                const float cq = topo[i * N_AGENT + jq];
                const float* gbv = bv + (size_t)(i * N_AGENT + jq) * HID;
                #pragma unroll
                for (int g = 0; g < HID; g++)
                    acc += sWa[tid * HID + g] * (cq * gbv[g]);
            }
            d_beff[i * A_DIM + tid] = acc;
        }
        return;
    }

    const int r0 = blockIdx.x * TBF;

    if (yb <= N_AGENT) {
        // ------- agent MLP: 64 row-threads x 2 output-halves, 2 rows each -------
        const int ag = yb - 1;
        const int rt = tid & 63, ch = tid >> 6;
        float* W1T  = sm;           // [48][40] (outputs padded to 40)
        float* W2T  = sm + 1920;    // [36][40]
        float* b1p  = sm + 3360;    // [40]
        float* b2p  = sm + 3400;    // [40]
        float* tile = sm + 3440;    // states: [128][52]; h: [128][44]
        float4* tile4 = (float4*)tile;

        const float* gW1 = W1 + ag * HID * S_DIM;
        for (int idx = tid; idx < S_DIM * 40; idx += NTHREADS) {
            const int k = idx / 40, f = idx - k * 40;
            W1T[idx] = (f < HID) ? gW1[f * S_DIM + k] : 0.f;
        }
        const float* gW2 = W2 + ag * HID * HID;
        for (int idx = tid; idx < HID * 40; idx += NTHREADS) {
            const int k = idx / 40, f = idx - k * 40;
            W2T[idx] = (f < HID) ? gW2[f * HID + k] : 0.f;
        }
        if (tid < 40) {
            b1p[tid] = (tid < HID) ? b1[ag * HID + tid] : 0.f;
            b2p[tid] = (tid < HID) ? b2[ag * HID + tid] : 0.f;
        }
        const float4* gS4 = (const float4*)(states + (size_t)(ag * BATCH + r0) * S_DIM);
        for (int idx = tid; idx < TBF * (S_DIM / 4); idx += NTHREADS) {
            const int row = idx / 12, c4 = idx - row * 12;
            tile4[row * 13 + c4] = gS4[idx];
        }
        __syncthreads();

        // layer 1: acc[r][p] = output f-pairs [ch*20, ch*20+20) for row rt+64r
        ull acc[2][10];
        {
            const ull* bb = (const ull*)(b1p + ch * 20);
            #pragma unroll
            for (int r = 0; r < 2; r++)
                #pragma unroll
                for (int p = 0; p < 10; p++) acc[r][p] = bb[p];
        }
        #pragma unroll
        for (int k4 = 0; k4 < S_DIM / 4; k4++) {
            float4 sv[2];
            #pragma unroll
            for (int r = 0; r < 2; r++) sv[r] = tile4[(rt + 64 * r) * 13 + k4];
            #pragma unroll
            for (int kk = 0; kk < 4; kk++) {
                const int k = k4 * 4 + kk;
                ull sk[2];
                #pragma unroll
                for (int r = 0; r < 2; r++) sk[r] = splat2(((const float*)&sv[r])[kk]);
                const ulonglong2* w = (const ulonglong2*)(W1T + k * 40 + ch * 20);
                #pragma unroll
                for (int p2 = 0; p2 < 5; p2++) {
                    ulonglong2 wv = w[p2];
                    #pragma unroll
                    for (int r = 0; r < 2; r++) {
                        acc[r][2*p2]   = fma2(wv.x, sk[r], acc[r][2*p2]);
                        acc[r][2*p2+1] = fma2(wv.y, sk[r], acc[r][2*p2+1]);
                    }
                }
            }
        }
        __syncthreads();   // states tile reads done
        // tanh -> h tile [128][44]
        #pragma unroll
        for (int r = 0; r < 2; r++) {
            float* hb = &tile[(rt + 64 * r) * 44 + ch * 20];
            #pragma unroll
            for (int p2 = 0; p2 < 5; p2++) {
                ulonglong2 st;
                st.x = tanh2(acc[r][2*p2]);
                st.y = tanh2(acc[r][2*p2+1]);
                *(ulonglong2*)&hb[4 * p2] = st;
            }
        }
        __syncthreads();

        // layer 2
        {
            const ull* bb = (const ull*)(b2p + ch * 20);
            #pragma unroll
            for (int r = 0; r < 2; r++)
                #pragma unroll
                for (int p = 0; p < 10; p++) acc[r][p] = bb[p];
        }
        #pragma unroll
        for (int k4 = 0; k4 < HID / 4; k4++) {
            float4 sv[2];
            #pragma unroll
            for (int r = 0; r < 2; r++) sv[r] = tile4[(rt + 64 * r) * 11 + k4];
            #pragma unroll
            for (int kk = 0; kk < 4; kk++) {
                const int k = k4 * 4 + kk;
                ull sk[2];
                #pragma unroll
                for (int r = 0; r < 2; r++) sk[r] = splat2(((const float*)&sv[r])[kk]);
                const ulonglong2* w = (const ulonglong2*)(W2T + k * 40 + ch * 20);
                #pragma unroll
                for (int p2 = 0; p2 < 5; p2++) {
                    ulonglong2 wv = w[p2];
                    #pragma unroll
                    for (int r = 0; r < 2; r++) {
                        acc[r][2*p2]   = fma2(wv.x, sk[r], acc[r][2*p2]);
                        acc[r][2*p2+1] = fma2(wv.y, sk[r], acc[r][2*p2+1]);
                    }
                }
            }
        }
        // tanh + TRANSPOSED store: pair p -> d_sfT[(ag*18+p)*8192 + row]
        // ch0 owns global pairs 0..9, ch1 owns 10..17 (local 0..7; 8,9 are pad)
        const int pb  = ch * 10;
        const int npr = ch ? 8 : 10;
        ull* sfT = (ull*)d_sfT;
        #pragma unroll
        for (int r = 0; r < 2; r++) {
            const int row = r0 + rt + 64 * r;
            for (int p2 = 0; p2 < npr; p2++)
                sfT[(size_t)(ag * 18 + pb + p2) * BATCH + row] = tanh2(acc[r][p2]);
        }
    } else {
        // ------- global feature, 1 row/thread, transposed store -------
        float* WgT = sm;           // [128][36]
        float* bgs = sm + 4608;
        for (int idx = tid; idx < HID * G_DIM; idx += NTHREADS) {
            const int f = idx / G_DIM, k = idx - f * G_DIM;
            WgT[k * HID + f] = Wg[idx];
        }
        if (tid < HID) bgs[tid] = bg[tid];
        __syncthreads();
        const int row = r0 + tid;
        ull acc0[18];
        {
            const ull* bu = (const ull*)bgs;
            #pragma unroll
            for (int p = 0; p < 18; p++) acc0[p] = bu[p];
        }
        const float4* g0 = (const float4*)(gs + (size_t)row * G_DIM);
        for (int k4 = 0; k4 < G_DIM / 4; k4++) {
            float4 vA = g0[k4];
            #pragma unroll
            for (int kk = 0; kk < 4; kk++) {
                const ull a_s = splat2(((const float*)&vA)[kk]);
                const ulonglong2* w = (const ulonglong2*)&WgT[(k4 * 4 + kk) * HID];
                #pragma unroll
                for (int p2 = 0; p2 < 9; p2++) {
                    ulonglong2 wv = w[p2];
                    acc0[2*p2]   = fma2(wv.x, a_s, acc0[2*p2]);
                    acc0[2*p2+1] = fma2(wv.y, a_s, acc0[2*p2+1]);
                }
            }
        }
        ull* gfT = (ull*)d_gfT;
        #pragma unroll
        for (int p = 0; p < 18; p++)
            gfT[(size_t)p * BATCH + row] = acc0[p];
    }
}

// ---------------------------------------------------------------------------
// comm: NO smem tiles. Activation pairs read directly via coalesced LDG.64
// from d_sfT / d_gfT; weights broadcast from 7KB smem. No mainloop barriers.
// 64 row-threads x 2 action-halves, 4 rows/thread.
// ---------------------------------------------------------------------------
__global__ __launch_bounds__(NTHREADS)
void comm_kernel(float* __restrict__ out)
{
    __shared__ __align__(16) float sA[4 * 432];
    __shared__ float sbe[16];
    const int tid = threadIdx.x;
    const int rt  = tid & 63, ch = tid >> 6;
    const int r0  = blockIdx.x * TBC;
    const int i   = blockIdx.y;

    const float4* gA = (const float4*)(d_A + (size_t)i * 4 * 432);
    float4* sA4 = (float4*)sA;
    for (int idx = tid; idx < 432; idx += NTHREADS) sA4[idx] = gA[idx];
    if (tid < A_DIM) sbe[tid] = d_beff[i * A_DIM + tid];
    __syncthreads();

    ull acc[4][5];
    #pragma unroll
    for (int r = 0; r < 4; r++)
        #pragma unroll
        for (int a = 0; a < 5; a++) acc[r][a] = 0ull;

    const int rbase = r0 + rt;
    for (int jj = 0; jj < 4; jj++) {
        const ull* src;
        if (jj < 3) {
            const int j = (i + N_AGENT - 1 + jj) & (N_AGENT - 1);
            src = (const ull*)d_sfT + (size_t)j * 18 * BATCH;
        } else {
            src = (const ull*)d_gfT;
        }
        const float* Ab = &sA[jj * 432];
        #pragma unroll 6
        for (int kp = 0; kp < 18; kp++) {
            ull s[4];
            const ull* sp = src + (size_t)kp * BATCH + rbase;
            #pragma unroll
            for (int r = 0; r < 4; r++) s[r] = sp[64 * r];
            const float* wp = Ab + kp * 24 + ch * 12;
            ulonglong2 w01 = *(const ulonglong2*)wp;
            ulonglong2 w23 = *(const ulonglong2*)(wp + 4);
            ull w4 = *(const ull*)(wp + 8);
            #pragma unroll
            for (int r = 0; r < 4; r++) {
                acc[r][0] = fma2(w01.x, s[r], acc[r][0]);
                acc[r][1] = fma2(w01.y, s[r], acc[r][1]);
                acc[r][2] = fma2(w23.x, s[r], acc[r][2]);
                acc[r][3] = fma2(w23.y, s[r], acc[r][3]);
                acc[r][4] = fma2(w4,    s[r], acc[r][4]);
            }
        }
    }

    #pragma unroll
    for (int r = 0; r < 4; r++) {
        const int row = r0 + rt + 64 * r;
        float acts[5];
        #pragma unroll
        for (int al = 0; al < 5; al++) {
            float2 p = unpack2(acc[r][al]);
            acts[al] = fast_tanh(p.x + p.y + sbe[ch * 5 + al]);
        }
        // alignment-aware epilogue: ch1's base offset is odd -> scalar first
        float* o = out + (size_t)row * (N_AGENT * A_DIM) + i * A_DIM + ch * 5;
        if (ch == 0) {
            *(float2*)o       = make_float2(acts[0], acts[1]);
            *(float2*)(o + 2) = make_float2(acts[2], acts[3]);
            o[4] = acts[4];
        } else {
            o[0] = acts[0];
            *(float2*)(o + 1) = make_float2(acts[1], acts[2]);
            *(float2*)(o + 3) = make_float2(acts[3], acts[4]);
        }
    }
}

extern "C" void kernel_launch(void* const* d_in, const int* in_sizes, int n_in,
                              void* d_out, int out_size)
{
    const float* states = (const float*)d_in[0];
    const float* gs     = (const float*)d_in[1];
    const float* W1     = (const float*)d_in[2];
    const float* b1     = (const float*)d_in[3];
    const float* W2     = (const float*)d_in[4];
    const float* b2     = (const float*)d_in[5];
    const float* Wv     = (const float*)d_in[6];
    const float* bv     = (const float*)d_in[7];
    const float* Wg     = (const float*)d_in[8];
    const float* bg     = (const float*)d_in[9];
    const float* Wact   = (const float*)d_in[10];
    const float* bact   = (const float*)d_in[11];
    const float* topo   = (const float*)d_in[12];

    cudaFuncSetAttribute(feat_kernel, cudaFuncAttributeMaxDynamicSharedMemorySize,
                         FEAT_SMEM_BYTES);
    feat_kernel<<<dim3(BATCH / TBF, N_AGENT + 2), NTHREADS, FEAT_SMEM_BYTES>>>(
        states, gs, W1, b1, W2, b2, Wg, bg, Wv, bv, Wact, bact, topo);
    comm_kernel<<<dim3(BATCH / TBC, N_AGENT), NTHREADS>>>((float*)d_out);
}

// round 12
// speedup vs baseline: 1.1955x; 1.0674x over previous
#include <cuda_runtime.h>

#define N_AGENT 32
#define BATCH   8192
#define S_DIM   48
#define A_DIM   10
#define G_DIM   128
#define HID     36
#define TBF     128       // rows per feat block
#define TBC     512       // rows per comm block
#define NTHREADS 128

typedef unsigned long long ull;

// Transposed pair-interleaved activations:
//   d_sfT: [agent][kp(18)][row(8192)] of 8B pairs (f=2kp, f=2kp+1)
//   d_gfT: [kp(18)][row(8192)] of 8B pairs
__device__ float d_sfT[N_AGENT * 18 * BATCH * 2];   // 37.7 MB
__device__ float d_gfT[18 * BATCH * 2];             // 1.2 MB
// A packed per (i, slice): [kp(18)][a2(5)][4]:
//   c0:(a=2a2,k=2kp) c1:(a=2a2,k=2kp+1) c2:(a=2a2+1,k=2kp) c3:(a=2a2+1,k=2kp+1)
__device__ float d_A[N_AGENT * 4 * 360];
__device__ float d_beff[N_AGENT * A_DIM];

__device__ __forceinline__ ull fma2(ull a, ull b, ull c) {
    ull d;
    asm("fma.rn.f32x2 %0, %1, %2, %3;" : "=l"(d) : "l"(a), "l"(b), "l"(c));
    return d;
}
__device__ __forceinline__ ull splat2(float x) {
    ull r; asm("mov.b64 %0, {%1, %1};" : "=l"(r) : "f"(x)); return r;
}
__device__ __forceinline__ ull pack2(float x, float y) {
    ull r; asm("mov.b64 %0, {%1, %2};" : "=l"(r) : "f"(x), "f"(y)); return r;
}
__device__ __forceinline__ float2 unpack2(ull v) {
    float2 r; asm("mov.b64 {%0, %1}, %2;" : "=f"(r.x), "=f"(r.y) : "l"(v)); return r;
}
__device__ __forceinline__ float fast_tanh(float x) {
    float e, r;
    asm("ex2.approx.f32 %0, %1;" : "=f"(e) : "f"(x * 2.88539008177793f)); // 2*log2(e)
    asm("rcp.approx.f32 %0, %1;" : "=f"(r) : "f"(e + 1.0f));
    return 1.0f - 2.0f * r;
}
__device__ __forceinline__ ull tanh2(ull v) {
    float2 p = unpack2(v);
    return pack2(fast_tanh(p.x), fast_tanh(p.y));
}

// ---------------------------------------------------------------------------
// feat: y==0 -> precompute packed A + beff; y in [1,32] -> agent MLP
// (split-output, 2 rows/thread, TBF=128); y==33 -> global feature.
// ---------------------------------------------------------------------------
#define FEAT_SMEM_FLOATS (3440 + TBF * 52)
#define FEAT_SMEM_BYTES  (FEAT_SMEM_FLOATS * 4)

__global__ void feat_kernel(const float* __restrict__ states,
                            const float* __restrict__ gs,
                            const float* __restrict__ W1, const float* __restrict__ b1,
                            const float* __restrict__ W2, const float* __restrict__ b2,
                            const float* __restrict__ Wg, const float* __restrict__ bg,
                            const float* __restrict__ Wv, const float* __restrict__ bv,
                            const float* __restrict__ Wact, const float* __restrict__ bact,
                            const float* __restrict__ topo)
{
    extern __shared__ __align__(16) float sm[];
    const int tid = threadIdx.x;
    const int yb  = blockIdx.y;

    if (yb == 0) {
        // ------- pre slice: packed A + beff for agent i = blockIdx.x -------
        const int i = blockIdx.x;
        if (i >= N_AGENT) return;
        float* sWa = sm;          // Wact_i [10][36]
        float* sWv = sm + 384;    // Wv     [36][36]
        for (int idx = tid; idx < A_DIM * HID; idx += NTHREADS)
            sWa[idx] = Wact[i * A_DIM * HID + idx];
        __syncthreads();
        for (int jj = 0; jj < 3; jj++) {
            const int j = (i + N_AGENT - 1 + jj) % N_AGENT;
            const float c = topo[i * N_AGENT + j];
            const float* gWv = Wv + (size_t)(i * N_AGENT + j) * HID * HID;
            for (int idx = tid; idx < HID * HID; idx += NTHREADS)
                sWv[idx] = c * gWv[idx];
            __syncthreads();
            for (int idx = tid; idx < 360; idx += NTHREADS) {
                const int kp = idx / 20, q = idx - kp * 20;
                const int a = 2 * (q >> 2) + ((q & 3) >> 1);
                const int k = 2 * kp + (q & 1);
                float acc = 0.f;
                #pragma unroll
                for (int g = 0; g < HID; g++)
                    acc += sWa[a * HID + g] * sWv[g * HID + k];
                d_A[(i * 4 + jj) * 360 + idx] = acc;
            }
            __syncthreads();
        }
        // slot 3 = plain Wact in packed layout (global-feature term)
        for (int idx = tid; idx < 360; idx += NTHREADS) {
            const int kp = idx / 20, q = idx - kp * 20;
            const int a = 2 * (q >> 2) + ((q & 3) >> 1);
            const int k = 2 * kp + (q & 1);
            d_A[(i * 4 + 3) * 360 + idx] = sWa[a * HID + k];
        }
        if (tid < A_DIM) {
            float acc = bact[i * A_DIM + tid];
            for (int q = 0; q < 3; q++) {
                const int jq = (i + N_AGENT - 1 + q) % N_AGENT;
                const float cq = topo[i * N_AGENT + jq];
                const float* gbv = bv + (size_t)(i * N_AGENT + jq) * HID;
                #pragma unroll
                for (int g = 0; g < HID; g++)
                    acc += sWa[tid * HID + g] * (cq * gbv[g]);
            }
            d_beff[i * A_DIM + tid] = acc;
        }
        return;
    }

    const int r0 = blockIdx.x * TBF;

    if (yb <= N_AGENT) {
        // ------- agent MLP: 64 row-threads x 2 output-halves, 2 rows each -------
        const int ag = yb - 1;
        const int rt = tid & 63, ch = tid >> 6;
        float* W1T  = sm;           // [48][40] (outputs padded to 40)
        float* W2T  = sm + 1920;    // [36][40]
        float* b1p  = sm + 3360;    // [40]
        float* b2p  = sm + 3400;    // [40]
        float* tile = sm + 3440;    // states: [128][52]; h: [128][44]
        float4* tile4 = (float4*)tile;

        const float* gW1 = W1 + ag * HID * S_DIM;
        for (int idx = tid; idx < S_DIM * 40; idx += NTHREADS) {
            const int k = idx / 40, f = idx - k * 40;
            W1T[idx] = (f < HID) ? gW1[f * S_DIM + k] : 0.f;
        }
        const float* gW2 = W2 + ag * HID * HID;
        for (int idx = tid; idx < HID * 40; idx += NTHREADS) {
            const int k = idx / 40, f = idx - k * 40;
            W2T[idx] = (f < HID) ? gW2[f * HID + k] : 0.f;
        }
        if (tid < 40) {
            b1p[tid] = (tid < HID) ? b1[ag * HID + tid] : 0.f;
            b2p[tid] = (tid < HID) ? b2[ag * HID + tid] : 0.f;
        }
        const float4* gS4 = (const float4*)(states + (size_t)(ag * BATCH + r0) * S_DIM);
        for (int idx = tid; idx < TBF * (S_DIM / 4); idx += NTHREADS) {
            const int row = idx / 12, c4 = idx - row * 12;
            tile4[row * 13 + c4] = gS4[idx];
        }
        __syncthreads();

        // layer 1: acc[r][p] = output f-pairs [ch*20, ch*20+20) for row rt+64r
        ull acc[2][10];
        {
            const ull* bb = (const ull*)(b1p + ch * 20);
            #pragma unroll
            for (int r = 0; r < 2; r++)
                #pragma unroll
                for (int p = 0; p < 10; p++) acc[r][p] = bb[p];
        }
        #pragma unroll
        for (int k4 = 0; k4 < S_DIM / 4; k4++) {
            float4 sv[2];
            #pragma unroll
            for (int r = 0; r < 2; r++) sv[r] = tile4[(rt + 64 * r) * 13 + k4];
            #pragma unroll
            for (int kk = 0; kk < 4; kk++) {
                const int k = k4 * 4 + kk;
                ull sk[2];
                #pragma unroll
                for (int r = 0; r < 2; r++) sk[r] = splat2(((const float*)&sv[r])[kk]);
                const ulonglong2* w = (const ulonglong2*)(W1T + k * 40 + ch * 20);
                #pragma unroll
                for (int p2 = 0; p2 < 5; p2++) {
                    ulonglong2 wv = w[p2];
                    #pragma unroll
                    for (int r = 0; r < 2; r++) {
                        acc[r][2*p2]   = fma2(wv.x, sk[r], acc[r][2*p2]);
                        acc[r][2*p2+1] = fma2(wv.y, sk[r], acc[r][2*p2+1]);
                    }
                }
            }
        }
        __syncthreads();   // states tile reads done
        // tanh -> h tile [128][44]
        #pragma unroll
        for (int r = 0; r < 2; r++) {
            float* hb = &tile[(rt + 64 * r) * 44 + ch * 20];
            #pragma unroll
            for (int p2 = 0; p2 < 5; p2++) {
                ulonglong2 st;
                st.x = tanh2(acc[r][2*p2]);
                st.y = tanh2(acc[r][2*p2+1]);
                *(ulonglong2*)&hb[4 * p2] = st;
            }
        }
        __syncthreads();

        // layer 2
        {
            const ull* bb = (const ull*)(b2p + ch * 20);
            #pragma unroll
            for (int r = 0; r < 2; r++)
                #pragma unroll
                for (int p = 0; p < 10; p++) acc[r][p] = bb[p];
        }
        #pragma unroll
        for (int k4 = 0; k4 < HID / 4; k4++) {
            float4 sv[2];
            #pragma unroll
            for (int r = 0; r < 2; r++) sv[r] = tile4[(rt + 64 * r) * 11 + k4];
            #pragma unroll
            for (int kk = 0; kk < 4; kk++) {
                const int k = k4 * 4 + kk;
                ull sk[2];
                #pragma unroll
                for (int r = 0; r < 2; r++) sk[r] = splat2(((const float*)&sv[r])[kk]);
                const ulonglong2* w = (const ulonglong2*)(W2T + k * 40 + ch * 20);
                #pragma unroll
                for (int p2 = 0; p2 < 5; p2++) {
                    ulonglong2 wv = w[p2];
                    #pragma unroll
                    for (int r = 0; r < 2; r++) {
                        acc[r][2*p2]   = fma2(wv.x, sk[r], acc[r][2*p2]);
                        acc[r][2*p2+1] = fma2(wv.y, sk[r], acc[r][2*p2+1]);
                    }
                }
            }
        }
        // tanh + TRANSPOSED store: pair p -> d_sfT[(ag*18+p)*8192 + row]
        // ch0 owns global pairs 0..9, ch1 owns 10..17 (local 0..7; 8,9 are pad)
        const int pb  = ch * 10;
        const int npr = ch ? 8 : 10;
        ull* sfT = (ull*)d_sfT;
        #pragma unroll
        for (int r = 0; r < 2; r++) {
            const int row = r0 + rt + 64 * r;
            for (int p2 = 0; p2 < npr; p2++)
                sfT[(size_t)(ag * 18 + pb + p2) * BATCH + row] = tanh2(acc[r][p2]);
        }
    } else {
        // ------- global feature, 1 row/thread, transposed store -------
        float* WgT = sm;           // [128][36]
        float* bgs = sm + 4608;
        for (int idx = tid; idx < HID * G_DIM; idx += NTHREADS) {
            const int f = idx / G_DIM, k = idx - f * G_DIM;
            WgT[k * HID + f] = Wg[idx];
        }
        if (tid < HID) bgs[tid] = bg[tid];
        __syncthreads();
        const int row = r0 + tid;
        ull acc0[18];
        {
            const ull* bu = (const ull*)bgs;
            #pragma unroll
            for (int p = 0; p < 18; p++) acc0[p] = bu[p];
        }
        const float4* g0 = (const float4*)(gs + (size_t)row * G_DIM);
        for (int k4 = 0; k4 < G_DIM / 4; k4++) {
            float4 vA = g0[k4];
            #pragma unroll
            for (int kk = 0; kk < 4; kk++) {
                const ull a_s = splat2(((const float*)&vA)[kk]);
                const ulonglong2* w = (const ulonglong2*)&WgT[(k4 * 4 + kk) * HID];
                #pragma unroll
                for (int p2 = 0; p2 < 9; p2++) {
                    ulonglong2 wv = w[p2];
                    acc0[2*p2]   = fma2(wv.x, a_s, acc0[2*p2]);
                    acc0[2*p2+1] = fma2(wv.y, a_s, acc0[2*p2+1]);
                }
            }
        }
        ull* gfT = (ull*)d_gfT;
        #pragma unroll
        for (int p = 0; p < 18; p++)
            gfT[(size_t)p * BATCH + row] = acc0[p];
    }
}

// ---------------------------------------------------------------------------
// comm: no ch-split (each thread owns all 10 actions for 4 rows), activation
// pairs via coalesced LDG.64 from d_sfT/d_gfT, weights broadcast from 5.8KB
// smem (5 LDS.128 per kp amortized over 4 rows = 40 fma2). TBC=512 -> grid
// 512 blocks <= 148x4 capacity -> single wave, no tail.
// ---------------------------------------------------------------------------
__global__ __launch_bounds__(NTHREADS, 4)
void comm_kernel(float* __restrict__ out)
{
    __shared__ __align__(16) float sA[4 * 360];
    __shared__ float sbe[16];
    const int tid = threadIdx.x;
    const int r0  = blockIdx.x * TBC;
    const int i   = blockIdx.y;

    const float4* gA = (const float4*)(d_A + (size_t)i * 4 * 360);
    float4* sA4 = (float4*)sA;
    for (int idx = tid; idx < 360; idx += NTHREADS) sA4[idx] = gA[idx];
    if (tid < A_DIM) sbe[tid] = d_beff[i * A_DIM + tid];
    __syncthreads();

    ull acc[4][A_DIM];
    #pragma unroll
    for (int r = 0; r < 4; r++)
        #pragma unroll
        for (int a = 0; a < A_DIM; a++) acc[r][a] = 0ull;

    const int rbase = r0 + tid;
    for (int jj = 0; jj < 4; jj++) {
        const ull* src;
        if (jj < 3) {
            const int j = (i + N_AGENT - 1 + jj) & (N_AGENT - 1);
            src = (const ull*)d_sfT + (size_t)j * 18 * BATCH;
        } else {
            src = (const ull*)d_gfT;
        }
        const float4* Aq = (const float4*)&sA[jj * 360];   // [kp][a2]
        #pragma unroll 3
        for (int kp = 0; kp < 18; kp++) {
            ull s[4];
            const ull* sp = src + (size_t)kp * BATCH + rbase;
            #pragma unroll
            for (int r = 0; r < 4; r++) s[r] = sp[NTHREADS * r];
            #pragma unroll
            for (int a2 = 0; a2 < 5; a2++) {
                float4 wq = Aq[kp * 5 + a2];
                ulonglong2 wu = *(ulonglong2*)&wq;
                #pragma unroll
                for (int r = 0; r < 4; r++) {
                    acc[r][2*a2]   = fma2(wu.x, s[r], acc[r][2*a2]);
                    acc[r][2*a2+1] = fma2(wu.y, s[r], acc[r][2*a2+1]);
                }
            }
        }
    }

    #pragma unroll
    for (int r = 0; r < 4; r++) {
        const int row = r0 + tid + NTHREADS * r;
        float2* o = (float2*)(out + (size_t)row * (N_AGENT * A_DIM) + i * A_DIM);
        #pragma unroll
        for (int p = 0; p < 5; p++) {
            float2 u = unpack2(acc[r][2*p]);
            float2 v = unpack2(acc[r][2*p+1]);
            o[p] = make_float2(fast_tanh(u.x + u.y + sbe[2*p]),
                               fast_tanh(v.x + v.y + sbe[2*p+1]));
        }
    }
}

extern "C" void kernel_launch(void* const* d_in, const int* in_sizes, int n_in,
                              void* d_out, int out_size)
{
    const float* states = (const float*)d_in[0];
    const float* gs     = (const float*)d_in[1];
    const float* W1     = (const float*)d_in[2];
    const float* b1     = (const float*)d_in[3];
    const float* W2     = (const float*)d_in[4];
    const float* b2     = (const float*)d_in[5];
    const float* Wv     = (const float*)d_in[6];
    const float* bv     = (const float*)d_in[7];
    const float* Wg     = (const float*)d_in[8];
    const float* bg     = (const float*)d_in[9];
    const float* Wact   = (const float*)d_in[10];
    const float* bact   = (const float*)d_in[11];
    const float* topo   = (const float*)d_in[12];

    cudaFuncSetAttribute(feat_kernel, cudaFuncAttributeMaxDynamicSharedMemorySize,
                         FEAT_SMEM_BYTES);
    feat_kernel<<<dim3(BATCH / TBF, N_AGENT + 2), NTHREADS, FEAT_SMEM_BYTES>>>(
        states, gs, W1, b1, W2, b2, Wg, bg, Wv, bv, Wact, bact, topo);
    comm_kernel<<<dim3(BATCH / TBC, N_AGENT), NTHREADS>>>((float*)d_out);
}

// round 13
// speedup vs baseline: 1.2028x; 1.0061x over previous
#include <cuda_runtime.h>

#define N_AGENT 32
#define BATCH   8192
#define S_DIM   48
#define A_DIM   10
#define G_DIM   128
#define HID     36
#define TBF     128       // rows per feat block
#define TBC     256       // rows per comm block
#define NTHREADS 128

typedef unsigned long long ull;

// Transposed pair-interleaved activations:
//   d_sfT: [agent][kp(18)][row(8192)] of 8B pairs (f=2kp, f=2kp+1)
//   d_gfT: [kp(18)][row(8192)] of 8B pairs
__device__ float d_sfT[N_AGENT * 18 * BATCH * 2];   // 37.7 MB
__device__ float d_gfT[18 * BATCH * 2];             // 1.2 MB
// A packed per (i, slice): [kp(18)][a2(5)][4]:
//   c0:(a=2a2,k=2kp) c1:(a=2a2,k=2kp+1) c2:(a=2a2+1,k=2kp) c3:(a=2a2+1,k=2kp+1)
__device__ float d_A[N_AGENT * 4 * 360];
__device__ float d_beff[N_AGENT * A_DIM];

__device__ __forceinline__ ull fma2(ull a, ull b, ull c) {
    ull d;
    asm("fma.rn.f32x2 %0, %1, %2, %3;" : "=l"(d) : "l"(a), "l"(b), "l"(c));
    return d;
}
__device__ __forceinline__ ull splat2(float x) {
    ull r; asm("mov.b64 %0, {%1, %1};" : "=l"(r) : "f"(x)); return r;
}
__device__ __forceinline__ ull pack2(float x, float y) {
    ull r; asm("mov.b64 %0, {%1, %2};" : "=l"(r) : "f"(x), "f"(y)); return r;
}
__device__ __forceinline__ float2 unpack2(ull v) {
    float2 r; asm("mov.b64 {%0, %1}, %2;" : "=f"(r.x), "=f"(r.y) : "l"(v)); return r;
}
__device__ __forceinline__ float fast_tanh(float x) {
    float e, r;
    asm("ex2.approx.f32 %0, %1;" : "=f"(e) : "f"(x * 2.88539008177793f)); // 2*log2(e)
    asm("rcp.approx.f32 %0, %1;" : "=f"(r) : "f"(e + 1.0f));
    return 1.0f - 2.0f * r;
}
__device__ __forceinline__ ull tanh2(ull v) {
    float2 p = unpack2(v);
    return pack2(fast_tanh(p.x), fast_tanh(p.y));
}

// ---------------------------------------------------------------------------
// feat: y==0 -> precompute packed A + beff; y in [1,32] -> agent MLP
// (split-output, 2 rows/thread, TBF=128); y==33 -> global feature.
// ---------------------------------------------------------------------------
#define FEAT_SMEM_FLOATS (3440 + TBF * 52)
#define FEAT_SMEM_BYTES  (FEAT_SMEM_FLOATS * 4)

__global__ void feat_kernel(const float* __restrict__ states,
                            const float* __restrict__ gs,
                            const float* __restrict__ W1, const float* __restrict__ b1,
                            const float* __restrict__ W2, const float* __restrict__ b2,
                            const float* __restrict__ Wg, const float* __restrict__ bg,
                            const float* __restrict__ Wv, const float* __restrict__ bv,
                            const float* __restrict__ Wact, const float* __restrict__ bact,
                            const float* __restrict__ topo)
{
    extern __shared__ __align__(16) float sm[];
    const int tid = threadIdx.x;
    const int yb  = blockIdx.y;

    if (yb == 0) {
        // ------- pre slice: packed A + beff for agent i = blockIdx.x -------
        const int i = blockIdx.x;
        if (i >= N_AGENT) return;
        float* sWa = sm;          // Wact_i [10][36]
        float* sWv = sm + 384;    // Wv     [36][36]
        for (int idx = tid; idx < A_DIM * HID; idx += NTHREADS)
            sWa[idx] = Wact[i * A_DIM * HID + idx];
        __syncthreads();
        for (int jj = 0; jj < 3; jj++) {
            const int j = (i + N_AGENT - 1 + jj) % N_AGENT;
            const float c = topo[i * N_AGENT + j];
            const float* gWv = Wv + (size_t)(i * N_AGENT + j) * HID * HID;
            for (int idx = tid; idx < HID * HID; idx += NTHREADS)
                sWv[idx] = c * gWv[idx];
            __syncthreads();
            for (int idx = tid; idx < 360; idx += NTHREADS) {
                const int kp = idx / 20, q = idx - kp * 20;
                const int a = 2 * (q >> 2) + ((q & 3) >> 1);
                const int k = 2 * kp + (q & 1);
                float acc = 0.f;
                #pragma unroll
                for (int g = 0; g < HID; g++)
                    acc += sWa[a * HID + g] * sWv[g * HID + k];
                d_A[(i * 4 + jj) * 360 + idx] = acc;
            }
            __syncthreads();
        }
        // slot 3 = plain Wact in packed layout (global-feature term)
        for (int idx = tid; idx < 360; idx += NTHREADS) {
            const int kp = idx / 20, q = idx - kp * 20;
            const int a = 2 * (q >> 2) + ((q & 3) >> 1);
            const int k = 2 * kp + (q & 1);
            d_A[(i * 4 + 3) * 360 + idx] = sWa[a * HID + k];
        }
        if (tid < A_DIM) {
            float acc = bact[i * A_DIM + tid];
            for (int q = 0; q < 3; q++) {
                const int jq = (i + N_AGENT - 1 + q) % N_AGENT;
                const float cq = topo[i * N_AGENT + jq];
                const float* gbv = bv + (size_t)(i * N_AGENT + jq) * HID;
                #pragma unroll
                for (int g = 0; g < HID; g++)
                    acc += sWa[tid * HID + g] * (cq * gbv[g]);
            }
            d_beff[i * A_DIM + tid] = acc;
        }
        return;
    }

    const int r0 = blockIdx.x * TBF;

    if (yb <= N_AGENT) {
        // ------- agent MLP: 64 row-threads x 2 output-halves, 2 rows each -------
        const int ag = yb - 1;
        const int rt = tid & 63, ch = tid >> 6;
        float* W1T  = sm;           // [48][40] (outputs padded to 40)
        float* W2T  = sm + 1920;    // [36][40]
        float* b1p  = sm + 3360;    // [40]
        float* b2p  = sm + 3400;    // [40]
        float* tile = sm + 3440;    // states: [128][52]; h: [128][44]
        float4* tile4 = (float4*)tile;

        const float* gW1 = W1 + ag * HID * S_DIM;
        for (int idx = tid; idx < S_DIM * 40; idx += NTHREADS) {
            const int k = idx / 40, f = idx - k * 40;
            W1T[idx] = (f < HID) ? gW1[f * S_DIM + k] : 0.f;
        }
        const float* gW2 = W2 + ag * HID * HID;
        for (int idx = tid; idx < HID * 40; idx += NTHREADS) {
            const int k = idx / 40, f = idx - k * 40;
            W2T[idx] = (f < HID) ? gW2[f * HID + k] : 0.f;
        }
        if (tid < 40) {
            b1p[tid] = (tid < HID) ? b1[ag * HID + tid] : 0.f;
            b2p[tid] = (tid < HID) ? b2[ag * HID + tid] : 0.f;
        }
        const float4* gS4 = (const float4*)(states + (size_t)(ag * BATCH + r0) * S_DIM);
        for (int idx = tid; idx < TBF * (S_DIM / 4); idx += NTHREADS) {
            const int row = idx / 12, c4 = idx - row * 12;
            tile4[row * 13 + c4] = gS4[idx];
        }
        __syncthreads();

        // layer 1: acc[r][p] = output f-pairs [ch*20, ch*20+20) for row rt+64r
        ull acc[2][10];
        {
            const ull* bb = (const ull*)(b1p + ch * 20);
            #pragma unroll
            for (int r = 0; r < 2; r++)
                #pragma unroll
                for (int p = 0; p < 10; p++) acc[r][p] = bb[p];
        }
        #pragma unroll
        for (int k4 = 0; k4 < S_DIM / 4; k4++) {
            float4 sv[2];
            #pragma unroll
            for (int r = 0; r < 2; r++) sv[r] = tile4[(rt + 64 * r) * 13 + k4];
            #pragma unroll
            for (int kk = 0; kk < 4; kk++) {
                const int k = k4 * 4 + kk;
                ull sk[2];
                #pragma unroll
                for (int r = 0; r < 2; r++) sk[r] = splat2(((const float*)&sv[r])[kk]);
                const ulonglong2* w = (const ulonglong2*)(W1T + k * 40 + ch * 20);
                #pragma unroll
                for (int p2 = 0; p2 < 5; p2++) {
                    ulonglong2 wv = w[p2];
                    #pragma unroll
                    for (int r = 0; r < 2; r++) {
                        acc[r][2*p2]   = fma2(wv.x, sk[r], acc[r][2*p2]);
                        acc[r][2*p2+1] = fma2(wv.y, sk[r], acc[r][2*p2+1]);
                    }
                }
            }
        }
        __syncthreads();   // states tile reads done
        // tanh -> h tile [128][44]
        #pragma unroll
        for (int r = 0; r < 2; r++) {
            float* hb = &tile[(rt + 64 * r) * 44 + ch * 20];
            #pragma unroll
            for (int p2 = 0; p2 < 5; p2++) {
                ulonglong2 st;
                st.x = tanh2(acc[r][2*p2]);
                st.y = tanh2(acc[r][2*p2+1]);
                *(ulonglong2*)&hb[4 * p2] = st;
            }
        }
        __syncthreads();

        // layer 2
        {
            const ull* bb = (const ull*)(b2p + ch * 20);
            #pragma unroll
            for (int r = 0; r < 2; r++)
                #pragma unroll
                for (int p = 0; p < 10; p++) acc[r][p] = bb[p];
        }
        #pragma unroll
        for (int k4 = 0; k4 < HID / 4; k4++) {
            float4 sv[2];
            #pragma unroll
            for (int r = 0; r < 2; r++) sv[r] = tile4[(rt + 64 * r) * 11 + k4];
            #pragma unroll
            for (int kk = 0; kk < 4; kk++) {
                const int k = k4 * 4 + kk;
                ull sk[2];
                #pragma unroll
                for (int r = 0; r < 2; r++) sk[r] = splat2(((const float*)&sv[r])[kk]);
                const ulonglong2* w = (const ulonglong2*)(W2T + k * 40 + ch * 20);
                #pragma unroll
                for (int p2 = 0; p2 < 5; p2++) {
                    ulonglong2 wv = w[p2];
                    #pragma unroll
                    for (int r = 0; r < 2; r++) {
                        acc[r][2*p2]   = fma2(wv.x, sk[r], acc[r][2*p2]);
                        acc[r][2*p2+1] = fma2(wv.y, sk[r], acc[r][2*p2+1]);
                    }
                }
            }
        }
        // tanh + TRANSPOSED store: pair p -> d_sfT[(ag*18+p)*8192 + row]
        // ch0 owns global pairs 0..9, ch1 owns 10..17 (local 0..7; 8,9 are pad)
        const int pb  = ch * 10;
        const int npr = ch ? 8 : 10;
        ull* sfT = (ull*)d_sfT;
        #pragma unroll
        for (int r = 0; r < 2; r++) {
            const int row = r0 + rt + 64 * r;
            for (int p2 = 0; p2 < npr; p2++)
                sfT[(size_t)(ag * 18 + pb + p2) * BATCH + row] = tanh2(acc[r][p2]);
        }
    } else {
        // ------- global feature, 1 row/thread, transposed store -------
        float* WgT = sm;           // [128][36]
        float* bgs = sm + 4608;
        for (int idx = tid; idx < HID * G_DIM; idx += NTHREADS) {
            const int f = idx / G_DIM, k = idx - f * G_DIM;
            WgT[k * HID + f] = Wg[idx];
        }
        if (tid < HID) bgs[tid] = bg[tid];
        __syncthreads();
        const int row = r0 + tid;
        ull acc0[18];
        {
            const ull* bu = (const ull*)bgs;
            #pragma unroll
            for (int p = 0; p < 18; p++) acc0[p] = bu[p];
        }
        const float4* g0 = (const float4*)(gs + (size_t)row * G_DIM);
        for (int k4 = 0; k4 < G_DIM / 4; k4++) {
            float4 vA = g0[k4];
            #pragma unroll
            for (int kk = 0; kk < 4; kk++) {
                const ull a_s = splat2(((const float*)&vA)[kk]);
                const ulonglong2* w = (const ulonglong2*)&WgT[(k4 * 4 + kk) * HID];
                #pragma unroll
                for (int p2 = 0; p2 < 9; p2++) {
                    ulonglong2 wv = w[p2];
                    acc0[2*p2]   = fma2(wv.x, a_s, acc0[2*p2]);
                    acc0[2*p2+1] = fma2(wv.y, a_s, acc0[2*p2+1]);
                }
            }
        }
        ull* gfT = (ull*)d_gfT;
        #pragma unroll
        for (int p = 0; p < 18; p++)
            gfT[(size_t)p * BATCH + row] = acc0[p];
    }
}

// ---------------------------------------------------------------------------
// comm: 2 rows/thread, 10 actions (pair-k accumulators, zero splats).
// acc = 20 ull = 40 regs -> ~64 total -> 8 blocks/SM (32 warps, 50% occ).
// TBC=256 -> grid 1024 <= 148*8 capacity -> single wave.
// ---------------------------------------------------------------------------
__global__ __launch_bounds__(NTHREADS, 8)
void comm_kernel(float* __restrict__ out)
{
    __shared__ __align__(16) float sA[4 * 360];
    __shared__ float sbe[16];
    const int tid = threadIdx.x;
    const int r0  = blockIdx.x * TBC;
    const int i   = blockIdx.y;

    const float4* gA = (const float4*)(d_A + (size_t)i * 4 * 360);
    float4* sA4 = (float4*)sA;
    for (int idx = tid; idx < 360; idx += NTHREADS) sA4[idx] = gA[idx];
    if (tid < A_DIM) sbe[tid] = d_beff[i * A_DIM + tid];
    __syncthreads();

    ull acc[2][A_DIM];
    #pragma unroll
    for (int r = 0; r < 2; r++)
        #pragma unroll
        for (int a = 0; a < A_DIM; a++) acc[r][a] = 0ull;

    const int rbase = r0 + tid;
    for (int jj = 0; jj < 4; jj++) {
        const ull* src;
        if (jj < 3) {
            const int j = (i + N_AGENT - 1 + jj) & (N_AGENT - 1);
            src = (const ull*)d_sfT + (size_t)j * 18 * BATCH;
        } else {
            src = (const ull*)d_gfT;
        }
        const float4* Aq = (const float4*)&sA[jj * 360];   // [kp][a2]
        const ull* sp = src + rbase;
        #pragma unroll 3
        for (int kp = 0; kp < 18; kp++) {
            ull s0 = sp[0];
            ull s1 = sp[NTHREADS];
            sp += BATCH;
            #pragma unroll
            for (int a2 = 0; a2 < 5; a2++) {
                float4 wq = Aq[kp * 5 + a2];
                ulonglong2 wu = *(ulonglong2*)&wq;
                acc[0][2*a2]   = fma2(wu.x, s0, acc[0][2*a2]);
                acc[0][2*a2+1] = fma2(wu.y, s0, acc[0][2*a2+1]);
                acc[1][2*a2]   = fma2(wu.x, s1, acc[1][2*a2]);
                acc[1][2*a2+1] = fma2(wu.y, s1, acc[1][2*a2+1]);
            }
        }
    }

    #pragma unroll
    for (int r = 0; r < 2; r++) {
        const int row = r0 + tid + NTHREADS * r;
        float2* o = (float2*)(out + (size_t)row * (N_AGENT * A_DIM) + i * A_DIM);
        #pragma unroll
        for (int p = 0; p < 5; p++) {
            float2 u = unpack2(acc[r][2*p]);
            float2 v = unpack2(acc[r][2*p+1]);
            o[p] = make_float2(fast_tanh(u.x + u.y + sbe[2*p]),
                               fast_tanh(v.x + v.y + sbe[2*p+1]));
        }
    }
}

extern "C" void kernel_launch(void* const* d_in, const int* in_sizes, int n_in,
                              void* d_out, int out_size)
{
    const float* states = (const float*)d_in[0];
    const float* gs     = (const float*)d_in[1];
    const float* W1     = (const float*)d_in[2];
    const float* b1     = (const float*)d_in[3];
    const float* W2     = (const float*)d_in[4];
    const float* b2     = (const float*)d_in[5];
    const float* Wv     = (const float*)d_in[6];
    const float* bv     = (const float*)d_in[7];
    const float* Wg     = (const float*)d_in[8];
    const float* bg     = (const float*)d_in[9];
    const float* Wact   = (const float*)d_in[10];
    const float* bact   = (const float*)d_in[11];
    const float* topo   = (const float*)d_in[12];

    cudaFuncSetAttribute(feat_kernel, cudaFuncAttributeMaxDynamicSharedMemorySize,
                         FEAT_SMEM_BYTES);
    feat_kernel<<<dim3(BATCH / TBF, N_AGENT + 2), NTHREADS, FEAT_SMEM_BYTES>>>(
        states, gs, W1, b1, W2, b2, Wg, bg, Wv, bv, Wact, bact, topo);
    comm_kernel<<<dim3(BATCH / TBC, N_AGENT), NTHREADS>>>((float*)d_out);
}